// round 4
// baseline (speedup 1.0000x reference)
#include <cuda_runtime.h>
#include <math.h>

#define NTOK 4096
#define DIM  1024
#define NEXP 8
#define CAP  1280
#define NSLOT (NTOK * 2)

// Scratch (no allocations allowed): expert ids per slot, inverse map (e,pos)->token.
__device__ int g_topidx[NSLOT];
__device__ int g_inv[NEXP * CAP];

// ---------------------------------------------------------------------------
// Kernel 1: logits = x @ W^T, top-2, softmax-of-2 -> gates (direct to out),
// expert ids -> g_topidx. One warp per token, W_gate staged in shared.
// ---------------------------------------------------------------------------
__global__ __launch_bounds__(256) void k_logits(const float* __restrict__ x,
                                                const float* __restrict__ Wg,
                                                float* __restrict__ gates) {
    __shared__ float4 sW[NEXP * DIM / 4];           // 32 KB
    const float4* W4 = (const float4*)Wg;
    for (int i = threadIdx.x; i < NEXP * DIM / 4; i += 256) sW[i] = W4[i];
    __syncthreads();

    int warp = threadIdx.x >> 5;
    int lane = threadIdx.x & 31;
    int t = blockIdx.x * 8 + warp;

    const float4* xr = (const float4*)x + (size_t)t * (DIM / 4);
    float acc[NEXP];
#pragma unroll
    for (int e = 0; e < NEXP; e++) acc[e] = 0.f;

#pragma unroll
    for (int i = 0; i < DIM / 128; i++) {           // 8 float4 per lane
        float4 v = xr[lane + 32 * i];
#pragma unroll
        for (int e = 0; e < NEXP; e++) {
            float4 w = sW[e * (DIM / 4) + lane + 32 * i];
            acc[e] += v.x * w.x + v.y * w.y + v.z * w.z + v.w * w.w;
        }
    }
#pragma unroll
    for (int off = 16; off; off >>= 1)
#pragma unroll
        for (int e = 0; e < NEXP; e++)
            acc[e] += __shfl_xor_sync(0xffffffffu, acc[e], off);

    if (lane == 0) {
        // top-2, ties -> lower index (matches jax.lax.top_k): strict > on ascending e
        float v1 = -1e30f, v2 = -1e30f;
        int i1 = 0, i2 = 0;
#pragma unroll
        for (int e = 0; e < NEXP; e++) {
            float a = acc[e];
            if (a > v1)      { v2 = v1; i2 = i1; v1 = a; i1 = e; }
            else if (a > v2) { v2 = a;  i2 = e; }
        }
        float e2 = expf(v2 - v1);
        float inv = 1.f / (1.f + e2);
        gates[2 * t]     = inv;        // softmax of (v1,v2), v1 is max
        gates[2 * t + 1] = e2 * inv;
        g_topidx[2 * t]     = i1;
        g_topidx[2 * t + 1] = i2;
    }
}

// ---------------------------------------------------------------------------
// Kernel 2 (single block): sequential-order position assignment via packed
// prefix scan over 8192 slots; scatter gates into exp_mask; build inverse map.
// ---------------------------------------------------------------------------
__global__ __launch_bounds__(256) void k_scan(const float* __restrict__ gates,
                                              float* __restrict__ mask) {
    int tid = threadIdx.x;

    // clear inverse map (barrier-ordered by the scan's __syncthreads below)
    for (int i = tid; i < NEXP * CAP; i += 256) g_inv[i] = -1;

    // local histogram over this thread's 32 consecutive slots
    int base = tid * 32;
    int e_loc[32];
    unsigned short h[NEXP];
#pragma unroll
    for (int e = 0; e < NEXP; e++) h[e] = 0;
#pragma unroll
    for (int j = 0; j < 32; j++) {
        int e = g_topidx[base + j];
        e_loc[j] = e;
        h[e]++;
    }

    // Hillis-Steele inclusive scan of 8x16-bit packed counters across 256 threads.
    // Max total count = 8192 < 65536 -> no inter-field carry.
    __shared__ uint4 ssc[256];
    uint4 v;
    v.x = (unsigned)h[0] | ((unsigned)h[1] << 16);
    v.y = (unsigned)h[2] | ((unsigned)h[3] << 16);
    v.z = (unsigned)h[4] | ((unsigned)h[5] << 16);
    v.w = (unsigned)h[6] | ((unsigned)h[7] << 16);
    ssc[tid] = v;
    __syncthreads();
    for (int off = 1; off < 256; off <<= 1) {
        uint4 a = make_uint4(0, 0, 0, 0);
        if (tid >= off) a = ssc[tid - off];
        __syncthreads();
        v.x += a.x; v.y += a.y; v.z += a.z; v.w += a.w;
        ssc[tid] = v;
        __syncthreads();
    }

    // exclusive prefix per expert for this thread = inclusive - own hist
    int cnt[NEXP];
    cnt[0] = (int)(v.x & 0xFFFF) - (int)h[0];
    cnt[1] = (int)(v.x >> 16)    - (int)h[1];
    cnt[2] = (int)(v.y & 0xFFFF) - (int)h[2];
    cnt[3] = (int)(v.y >> 16)    - (int)h[3];
    cnt[4] = (int)(v.z & 0xFFFF) - (int)h[4];
    cnt[5] = (int)(v.z >> 16)    - (int)h[5];
    cnt[6] = (int)(v.w & 0xFFFF) - (int)h[6];
    cnt[7] = (int)(v.w >> 16)    - (int)h[7];

    // replay in order: assign positions, scatter gate into mask, fill inverse map
#pragma unroll
    for (int j = 0; j < 32; j++) {
        int slot = base + j;
        int e = e_loc[j];
        int p = cnt[e]++;
        if (p < CAP) {
            int tok = slot >> 1;
            mask[(size_t)tok * (NEXP * CAP) + e * CAP + p] = gates[slot];
            g_inv[e * CAP + p] = tok;
        }
    }
}

// ---------------------------------------------------------------------------
// Kernel 3: write exp_batches fully (copy token row or zeros) — one block per
// (expert, position) row, 256 threads x float4 = 1024 floats.
// ---------------------------------------------------------------------------
__global__ __launch_bounds__(256) void k_batch(const float* __restrict__ x,
                                               float* __restrict__ batch) {
    int r = blockIdx.x;                 // 0 .. NEXP*CAP-1
    int t = g_inv[r];
    float4* dst = (float4*)batch + (size_t)r * (DIM / 4);
    if (t >= 0) {
        const float4* src = (const float4*)x + (size_t)t * (DIM / 4);
        dst[threadIdx.x] = src[threadIdx.x];
    } else {
        dst[threadIdx.x] = make_float4(0.f, 0.f, 0.f, 0.f);
    }
}

// ---------------------------------------------------------------------------
extern "C" void kernel_launch(void* const* d_in, const int* in_sizes, int n_in,
                              void* d_out, int out_size) {
    const float* x  = (const float*)d_in[0];   // [2,2048,1024] f32
    const float* Wg = (const float*)d_in[1];   // [8,1024] f32

    float* out   = (float*)d_out;
    float* gates = out;                                    // 8192 floats
    float* mask  = out + (size_t)NSLOT;                    // 41,943,040 floats
    float* batch = mask + (size_t)NTOK * NEXP * CAP;       // 10,485,760 floats

    // Zero exp_mask first so x stays L2-resident between k_logits and k_batch.
    cudaMemsetAsync(mask, 0, (size_t)NTOK * NEXP * CAP * sizeof(float), 0);

    k_logits<<<NTOK / 8, 256>>>(x, Wg, gates);
    k_scan<<<1, 256>>>(gates, mask);
    k_batch<<<NEXP * CAP, 256>>>(x, batch);
}

// round 5
// speedup vs baseline: 1.1654x; 1.1654x over previous
#include <cuda_runtime.h>
#include <math.h>

#define NTOK 4096
#define DIM  1024
#define NEXP 8
#define CAP  1280
#define NSLOT (NTOK * 2)
#define ROWW (NEXP * CAP)          // 10240 floats per mask token-row

// Scratch (no device allocs allowed)
__device__ int g_topidx[NSLOT];    // expert id per slot
__device__ int g_pos[NSLOT];       // position within expert, -1 if dropped
__device__ int g_inv[NEXP * CAP];  // (e,pos) -> token, -1 if empty

// ---------------------------------------------------------------------------
// Kernel 1: logits = x @ W^T, top-2, softmax-of-2. 4 tokens per warp to
// amortize shared-memory W traffic and expose FMA ILP.
// ---------------------------------------------------------------------------
__global__ __launch_bounds__(256) void k_logits(const float* __restrict__ x,
                                                const float* __restrict__ Wg,
                                                float* __restrict__ gates) {
    __shared__ float4 sW[NEXP * DIM / 4];            // 32 KB
    const float4* W4 = (const float4*)Wg;
    for (int i = threadIdx.x; i < NEXP * DIM / 4; i += 256) sW[i] = W4[i];
    __syncthreads();

    int warp = threadIdx.x >> 5;
    int lane = threadIdx.x & 31;
    int t0 = (blockIdx.x * 8 + warp) * 4;            // 4 tokens per warp

    const float4* xr = (const float4*)x + (size_t)t0 * (DIM / 4);
    float acc[4][NEXP];
#pragma unroll
    for (int j = 0; j < 4; j++)
#pragma unroll
        for (int e = 0; e < NEXP; e++) acc[j][e] = 0.f;

#pragma unroll
    for (int i = 0; i < DIM / 128; i++) {            // 8 iterations
        int o = lane + 32 * i;
        float4 v0 = xr[o];
        float4 v1 = xr[256 + o];
        float4 v2 = xr[512 + o];
        float4 v3 = xr[768 + o];
#pragma unroll
        for (int e = 0; e < NEXP; e++) {
            float4 w = sW[e * 256 + o];
            acc[0][e] += v0.x * w.x + v0.y * w.y + v0.z * w.z + v0.w * w.w;
            acc[1][e] += v1.x * w.x + v1.y * w.y + v1.z * w.z + v1.w * w.w;
            acc[2][e] += v2.x * w.x + v2.y * w.y + v2.z * w.z + v2.w * w.w;
            acc[3][e] += v3.x * w.x + v3.y * w.y + v3.z * w.z + v3.w * w.w;
        }
    }
#pragma unroll
    for (int off = 16; off; off >>= 1)
#pragma unroll
        for (int j = 0; j < 4; j++)
#pragma unroll
            for (int e = 0; e < NEXP; e++)
                acc[j][e] += __shfl_xor_sync(0xffffffffu, acc[j][e], off);

    if (lane < 4) {                                  // lane j finalizes token t0+j
        int t = t0 + lane;
        float v1 = -1e30f, v2 = -1e30f;
        int i1 = 0, i2 = 0;
#pragma unroll
        for (int e = 0; e < NEXP; e++) {
            float a = acc[lane][e];
            if (a > v1)      { v2 = v1; i2 = i1; v1 = a; i1 = e; }
            else if (a > v2) { v2 = a;  i2 = e; }
        }
        float e2 = expf(v2 - v1);
        float inv = 1.f / (1.f + e2);
        gates[2 * t]     = inv;
        gates[2 * t + 1] = e2 * inv;
        g_topidx[2 * t]     = i1;
        g_topidx[2 * t + 1] = i2;
    }
}

// ---------------------------------------------------------------------------
// Kernel 2 (single block): serial-order position assignment via packed
// 8x16-bit prefix scan over 8192 slots. Writes g_pos and g_inv only.
// ---------------------------------------------------------------------------
__global__ __launch_bounds__(256) void k_scan() {
    int tid = threadIdx.x;

    for (int i = tid; i < NEXP * CAP; i += 256) g_inv[i] = -1;

    int base = tid * 32;
    int e_loc[32];
    unsigned short h[NEXP];
#pragma unroll
    for (int e = 0; e < NEXP; e++) h[e] = 0;
#pragma unroll
    for (int j = 0; j < 32; j++) {
        int e = g_topidx[base + j];
        e_loc[j] = e;
        h[e]++;
    }

    __shared__ uint4 ssc[256];
    uint4 v;
    v.x = (unsigned)h[0] | ((unsigned)h[1] << 16);
    v.y = (unsigned)h[2] | ((unsigned)h[3] << 16);
    v.z = (unsigned)h[4] | ((unsigned)h[5] << 16);
    v.w = (unsigned)h[6] | ((unsigned)h[7] << 16);
    ssc[tid] = v;
    __syncthreads();
    for (int off = 1; off < 256; off <<= 1) {
        uint4 a = make_uint4(0, 0, 0, 0);
        if (tid >= off) a = ssc[tid - off];
        __syncthreads();
        v.x += a.x; v.y += a.y; v.z += a.z; v.w += a.w;
        ssc[tid] = v;
        __syncthreads();
    }

    int cnt[NEXP];
    cnt[0] = (int)(v.x & 0xFFFF) - (int)h[0];
    cnt[1] = (int)(v.x >> 16)    - (int)h[1];
    cnt[2] = (int)(v.y & 0xFFFF) - (int)h[2];
    cnt[3] = (int)(v.y >> 16)    - (int)h[3];
    cnt[4] = (int)(v.z & 0xFFFF) - (int)h[4];
    cnt[5] = (int)(v.z >> 16)    - (int)h[5];
    cnt[6] = (int)(v.w & 0xFFFF) - (int)h[6];
    cnt[7] = (int)(v.w >> 16)    - (int)h[7];

#pragma unroll
    for (int j = 0; j < 32; j++) {
        int slot = base + j;
        int e = e_loc[j];
        int p = cnt[e]++;
        if (p < CAP) {
            g_pos[slot] = p;
            g_inv[e * CAP + p] = slot >> 1;
        } else {
            g_pos[slot] = -1;
        }
    }
}

// ---------------------------------------------------------------------------
// Kernel 3: write ALL of exp_batches and exp_mask exactly once, streaming
// stores. Batch rows first (x still hot in L2 from k_logits), mask rows after.
// ---------------------------------------------------------------------------
__global__ __launch_bounds__(256) void k_out(const float* __restrict__ x,
                                             const float* __restrict__ gates,
                                             float* __restrict__ mask,
                                             float* __restrict__ batch) {
    int b = blockIdx.x;
    if (b < NEXP * CAP) {
        // exp_batches row: copy token or zeros (1024 floats = 256 x float4)
        int t = g_inv[b];
        float4 v = make_float4(0.f, 0.f, 0.f, 0.f);
        if (t >= 0)
            v = ((const float4*)x)[(size_t)t * (DIM / 4) + threadIdx.x];
        __stcs((float4*)batch + (size_t)b * (DIM / 4) + threadIdx.x, v);
    } else {
        // exp_mask token-row: 10240 floats, <=2 nonzeros at known offsets
        int tok = b - NEXP * CAP;
        int e0 = g_topidx[2 * tok],     e1 = g_topidx[2 * tok + 1];
        int p0 = g_pos[2 * tok],        p1 = g_pos[2 * tok + 1];
        float g0 = gates[2 * tok],      g1 = gates[2 * tok + 1];
        int off0 = (p0 >= 0) ? e0 * CAP + p0 : -1;
        int off1 = (p1 >= 0) ? e1 * CAP + p1 : -1;
        float4* dst = (float4*)mask + (size_t)tok * (ROWW / 4);
#pragma unroll
        for (int j = 0; j < (ROWW / 4) / 256; j++) { // 10 iterations
            int i4 = j * 256 + threadIdx.x;
            int w = i4 * 4;
            float4 v = make_float4(0.f, 0.f, 0.f, 0.f);
            if (off0 >= w && off0 < w + 4) ((float*)&v)[off0 - w] = g0;
            if (off1 >= w && off1 < w + 4) ((float*)&v)[off1 - w] = g1;
            __stcs(dst + i4, v);
        }
    }
}

// ---------------------------------------------------------------------------
extern "C" void kernel_launch(void* const* d_in, const int* in_sizes, int n_in,
                              void* d_out, int out_size) {
    const float* x  = (const float*)d_in[0];   // [2,2048,1024] f32
    const float* Wg = (const float*)d_in[1];   // [8,1024] f32

    float* out   = (float*)d_out;
    float* gates = out;                                  // 8,192 floats
    float* mask  = out + (size_t)NSLOT;                  // 41,943,040 floats
    float* batch = mask + (size_t)NTOK * ROWW;           // 10,485,760 floats

    k_logits<<<NTOK / 32, 256>>>(x, Wg, gates);          // 128 blocks
    k_scan<<<1, 256>>>();
    k_out<<<NEXP * CAP + NTOK, 256>>>(x, gates, mask, batch);  // 14336 blocks
}